// round 8
// baseline (speedup 1.0000x reference)
#include <cuda_runtime.h>
#include <cuda_fp16.h>
#include <cstdint>

// Conv2d 3x3 VALID, C_in=C_out=8, 2048x2048 fp32 -> (8, 2046, 2046)
// Round 8: mma.sync m16n8k16 **fp16** conv, ONE MMA per tap:
//   x = x_hi + x_lo (fp16 each, exact to 2^-22), folded into K:
//     k even = x_hi, k odd = x_lo ; B = (w_f16, w_f16)
//   => product = x * w_f16 ; only error is w rounding (~2^-12).
// 3 output rows per warp share 5 staged input rows (LDS reuse).

#define CIN   8
#define COUT  8
#define IH    2048
#define IW    2048
#define OHH   2046
#define OWW   2046
#define CH    (IH*IW)
#define TPX   128
#define RPW   3            // output rows per warp
#define TR    12           // output rows per block (4 warps x 3)
#define INR   14           // TR + 2 input rows staged
#define INPX  130
#define ROWSTRIDE (INPX*8) // u32 per staged row

typedef uint32_t u32;

__device__ __forceinline__ u32 f16_hi_lo_pack(float v) {
    __half hb = __float2half_rn(v);
    float hf = __half2float(hb);
    __half lb = __float2half_rn(v - hf);
    return (u32)__half_as_ushort(hb) | ((u32)__half_as_ushort(lb) << 16);
}

__device__ __forceinline__ void mma16816(float* d,
                                         u32 a0, u32 a1, u32 a2, u32 a3,
                                         u32 b0, u32 b1) {
    asm volatile(
        "mma.sync.aligned.m16n8k16.row.col.f32.f16.f16.f32 "
        "{%0,%1,%2,%3}, {%4,%5,%6,%7}, {%8,%9}, {%0,%1,%2,%3};"
        : "+f"(d[0]), "+f"(d[1]), "+f"(d[2]), "+f"(d[3])
        : "r"(a0), "r"(a1), "r"(a2), "r"(a3), "r"(b0), "r"(b1));
}

__global__ __launch_bounds__(128)
void conv3x3_mma_kernel(const float* __restrict__ x,
                        const float* __restrict__ w,
                        float* __restrict__ out) {
    // stage[row][px][s]: s = cin interleaved, (cin q, q+4) adjacent ->
    // one LDS.64 gives a thread's two A-fragment words. 32B pixel stride.
    extern __shared__ u32 stage[];   // [INR][INPX][8]

    const int tid  = threadIdx.x;
    const int wid  = tid >> 5;
    const int lane = tid & 31;
    const int gid  = lane >> 2;   // 0..7 : fragment row / cout
    const int q    = lane & 3;    // 0..3 : k-pair / cin selector

    int x0 = blockIdx.x * TPX; if (x0 > OWW - TPX) x0 = OWW - TPX;
    int y0 = blockIdx.y * TR;  if (y0 > OHH - TR)  y0 = OHH - TR;

    // ---- weight fragments: co = gid, cin = q (+4), B word = (w, w) ----
    u32 bw[9][2];
    #pragma unroll
    for (int i = 0; i < 9; ++i) {
        int ky = i / 3, kx = i % 3;
        #pragma unroll
        for (int h = 0; h < 2; ++h) {
            int cin = q + 4 * h;
            float wv = __ldg(&w[((gid * CIN + cin) * 3 + ky) * 3 + kx]);
            u32 wu = __half_as_ushort(__float2half_rn(wv));
            bw[i][h] = wu | (wu << 16);
        }
    }

    // ---- stage inputs: fp16 hi/lo split, cin-interleaved ----
    for (int it = tid; it < INR * INPX; it += 128) {
        int b  = it / INPX;
        int xl = it - b * INPX;
        const float* ip = x + (size_t)(y0 + b) * IW + (x0 + xl);
        u32 sv[8];
        #pragma unroll
        for (int c = 0; c < 8; ++c) {
            u32 pk = f16_hi_lo_pack(__ldg(ip + (size_t)c * CH));
            sv[(c & 3) * 2 + (c >> 2)] = pk;
        }
        uint4* dst = reinterpret_cast<uint4*>(&stage[(size_t)b * ROWSTRIDE + (size_t)xl * 8]);
        dst[0] = make_uint4(sv[0], sv[1], sv[2], sv[3]);
        dst[1] = make_uint4(sv[4], sv[5], sv[6], sv[7]);
    }
    __syncthreads();

    // ---- compute: warp handles output rows y0+3*wid .. +2 ----
    const size_t PL = (size_t)OHH * OWW;
    const int r0 = y0 + RPW * wid;

    const u32* rbase[RPW + 2];
    #pragma unroll
    for (int ir = 0; ir < RPW + 2; ++ir)
        rbase[ir] = &stage[(size_t)(RPW * wid + ir) * ROWSTRIDE + (size_t)gid * 8 + 2 * q];

    #pragma unroll 1
    for (int chunk = 0; chunk < 8; ++chunk) {
        float a0[4] = {0,0,0,0};
        float a1[4] = {0,0,0,0};
        float a2[4] = {0,0,0,0};
        const int co = chunk * 16 * 8;   // u32 offset of chunk base pixel

        #pragma unroll
        for (int ir = 0; ir < RPW + 2; ++ir) {   // 5 distinct input rows
            const u32* rp = rbase[ir] + co;
            uint2 lo[3], hi[3];
            #pragma unroll
            for (int kx = 0; kx < 3; ++kx) {
                lo[kx] = *reinterpret_cast<const uint2*>(rp + kx * 8);
                hi[kx] = *reinterpret_cast<const uint2*>(rp + (kx + 8) * 8);
            }
            #pragma unroll
            for (int kx = 0; kx < 3; ++kx) {
                u32 f0 = lo[kx].x, f1 = hi[kx].x, f2 = lo[kx].y, f3 = hi[kx].y;
                if (ir < 3)               // row0: ky = ir
                    mma16816(a0, f0, f1, f2, f3, bw[ir*3+kx][0],     bw[ir*3+kx][1]);
                if (ir >= 1 && ir <= 3)   // row1: ky = ir-1
                    mma16816(a1, f0, f1, f2, f3, bw[(ir-1)*3+kx][0], bw[(ir-1)*3+kx][1]);
                if (ir >= 2)              // row2: ky = ir-2
                    mma16816(a2, f0, f1, f2, f3, bw[(ir-2)*3+kx][0], bw[(ir-2)*3+kx][1]);
            }
        }

        // D: [0]=D[gid][2q] [1]=D[gid][2q+1] [2]=D[gid+8][2q] [3]=D[gid+8][2q+1]
        int pix = x0 + chunk * 16 + gid;
        float* op = out + (size_t)(2 * q) * PL + (size_t)r0 * OWW + pix;
        op[0]      = a0[0];  op[PL]     = a0[1];
        op[8]      = a0[2];  op[PL + 8] = a0[3];
        op += OWW;
        op[0]      = a1[0];  op[PL]     = a1[1];
        op[8]      = a1[2];  op[PL + 8] = a1[3];
        op += OWW;
        op[0]      = a2[0];  op[PL]     = a2[1];
        op[8]      = a2[2];  op[PL + 8] = a2[3];
    }
}

extern "C" void kernel_launch(void* const* d_in, const int* in_sizes, int n_in,
                              void* d_out, int out_size) {
    const float* x = (const float*)d_in[0];   // (8, 2048, 2048) fp32
    const float* w = (const float*)d_in[1];   // (8, 8, 3, 3) fp32
    float* out = (float*)d_out;               // (8, 2046, 2046) fp32

    const int smem = INR * INPX * 8 * 4;      // 58240 B
    static int configured = 0;
    if (!configured) {
        cudaFuncSetAttribute(conv3x3_mma_kernel,
                             cudaFuncAttributeMaxDynamicSharedMemorySize, smem);
        configured = 1;
    }
    dim3 grid(16, (OHH + TR - 1) / TR);       // 16 x 171, edges clamped
    conv3x3_mma_kernel<<<grid, 128, smem>>>(x, w, out);
}

// round 9
// speedup vs baseline: 1.2678x; 1.2678x over previous
#include <cuda_runtime.h>
#include <cuda_fp16.h>
#include <cstdint>

// Conv2d 3x3 VALID, C_in=C_out=8, 2048x2048 fp32 -> (8, 2046, 2046)
// Round 9: fp16 single-MMA-per-tap conv (x = hi+lo fp16 in K slots,
// B=(w,w)), 256 threads / 8 warps / 2 output rows per warp for occupancy,
// 2 interleaved accumulator chains.

#define CIN   8
#define COUT  8
#define IH    2048
#define IW    2048
#define OHH   2046
#define OWW   2046
#define CH    (IH*IW)
#define TPX   128
#define NW    8            // warps per block
#define RPW   2            // output rows per warp
#define TR    (NW*RPW)     // 16 output rows per block
#define INR   (TR+2)       // 18 input rows staged
#define INPX  130
#define ROWSTRIDE (INPX*8) // u32 per staged row
#define NTHREADS  (NW*32)

typedef uint32_t u32;

__device__ __forceinline__ u32 f16_hi_lo_pack(float v) {
    __half hb = __float2half_rn(v);
    float hf = __half2float(hb);
    __half lb = __float2half_rn(v - hf);
    return (u32)__half_as_ushort(hb) | ((u32)__half_as_ushort(lb) << 16);
}

__device__ __forceinline__ void mma16816(float* d,
                                         u32 a0, u32 a1, u32 a2, u32 a3,
                                         u32 b0, u32 b1) {
    asm volatile(
        "mma.sync.aligned.m16n8k16.row.col.f32.f16.f16.f32 "
        "{%0,%1,%2,%3}, {%4,%5,%6,%7}, {%8,%9}, {%0,%1,%2,%3};"
        : "+f"(d[0]), "+f"(d[1]), "+f"(d[2]), "+f"(d[3])
        : "r"(a0), "r"(a1), "r"(a2), "r"(a3), "r"(b0), "r"(b1));
}

__global__ __launch_bounds__(NTHREADS)
void conv3x3_mma_kernel(const float* __restrict__ x,
                        const float* __restrict__ w,
                        float* __restrict__ out) {
    // stage[row][px][s]: s = cin interleaved, (cin q, q+4) adjacent -> one
    // LDS.64 gives a thread's two A-fragment words. 32B pixel stride.
    extern __shared__ u32 stage[];   // [INR][INPX][8]

    const int tid  = threadIdx.x;
    const int wid  = tid >> 5;
    const int lane = tid & 31;
    const int gid  = lane >> 2;   // 0..7 : fragment row / cout
    const int q    = lane & 3;    // 0..3 : k-pair / cin selector

    int x0 = blockIdx.x * TPX; if (x0 > OWW - TPX) x0 = OWW - TPX;
    int y0 = blockIdx.y * TR;  if (y0 > OHH - TR)  y0 = OHH - TR;

    // ---- weight fragments: co = gid, cin = q (+4), B word = (w, w) ----
    u32 bw[9][2];
    #pragma unroll
    for (int i = 0; i < 9; ++i) {
        int ky = i / 3, kx = i % 3;
        #pragma unroll
        for (int h = 0; h < 2; ++h) {
            int cin = q + 4 * h;
            float wv = __ldg(&w[((gid * CIN + cin) * 3 + ky) * 3 + kx]);
            u32 wu = __half_as_ushort(__float2half_rn(wv));
            bw[i][h] = wu | (wu << 16);
        }
    }

    // ---- stage inputs: fp16 hi/lo split, cin-interleaved ----
    for (int it = tid; it < INR * INPX; it += NTHREADS) {
        int b  = it / INPX;
        int xl = it - b * INPX;
        const float* ip = x + (size_t)(y0 + b) * IW + (x0 + xl);
        u32 sv[8];
        #pragma unroll
        for (int c = 0; c < 8; ++c) {
            u32 pk = f16_hi_lo_pack(__ldg(ip + (size_t)c * CH));
            sv[(c & 3) * 2 + (c >> 2)] = pk;
        }
        uint4* dst = reinterpret_cast<uint4*>(&stage[(size_t)b * ROWSTRIDE + (size_t)xl * 8]);
        dst[0] = make_uint4(sv[0], sv[1], sv[2], sv[3]);
        dst[1] = make_uint4(sv[4], sv[5], sv[6], sv[7]);
    }
    __syncthreads();

    // ---- compute: warp handles output rows y0+2*wid, +1 ----
    const size_t PL = (size_t)OHH * OWW;
    const int r0 = y0 + RPW * wid;

    const u32* rbase[RPW + 2];
    #pragma unroll
    for (int ir = 0; ir < RPW + 2; ++ir)
        rbase[ir] = &stage[(size_t)(RPW * wid + ir) * ROWSTRIDE + (size_t)gid * 8 + 2 * q];

    #pragma unroll 1
    for (int chunk = 0; chunk < 8; ++chunk) {
        float a0[4] = {0,0,0,0};
        float a1[4] = {0,0,0,0};
        const int co = chunk * 16 * 8;   // u32 offset of chunk base pixel

        #pragma unroll
        for (int ir = 0; ir < RPW + 2; ++ir) {   // 4 distinct input rows
            const u32* rp = rbase[ir] + co;
            uint2 lo[3], hi[3];
            #pragma unroll
            for (int kx = 0; kx < 3; ++kx) {
                lo[kx] = *reinterpret_cast<const uint2*>(rp + kx * 8);
                hi[kx] = *reinterpret_cast<const uint2*>(rp + (kx + 8) * 8);
            }
            // interleave the two chains
            #pragma unroll
            for (int kx = 0; kx < 3; ++kx) {
                u32 f0 = lo[kx].x, f1 = hi[kx].x, f2 = lo[kx].y, f3 = hi[kx].y;
                if (ir < 3)
                    mma16816(a0, f0, f1, f2, f3, bw[ir*3+kx][0], bw[ir*3+kx][1]);
                if (ir >= 1)
                    mma16816(a1, f0, f1, f2, f3, bw[(ir-1)*3+kx][0], bw[(ir-1)*3+kx][1]);
            }
        }

        // D: [0]=D[gid][2q] [1]=D[gid][2q+1] [2]=D[gid+8][2q] [3]=D[gid+8][2q+1]
        int pix = x0 + chunk * 16 + gid;
        float* op = out + (size_t)(2 * q) * PL + (size_t)r0 * OWW + pix;
        op[0]      = a0[0];  op[PL]     = a0[1];
        op[8]      = a0[2];  op[PL + 8] = a0[3];
        op += OWW;
        op[0]      = a1[0];  op[PL]     = a1[1];
        op[8]      = a1[2];  op[PL + 8] = a1[3];
    }
}

extern "C" void kernel_launch(void* const* d_in, const int* in_sizes, int n_in,
                              void* d_out, int out_size) {
    const float* x = (const float*)d_in[0];   // (8, 2048, 2048) fp32
    const float* w = (const float*)d_in[1];   // (8, 8, 3, 3) fp32
    float* out = (float*)d_out;               // (8, 2046, 2046) fp32

    const int smem = INR * INPX * 8 * 4;      // 74880 B
    static int configured = 0;
    if (!configured) {
        cudaFuncSetAttribute(conv3x3_mma_kernel,
                             cudaFuncAttributeMaxDynamicSharedMemorySize, smem);
        configured = 1;
    }
    dim3 grid(16, (OHH + TR - 1) / TR);       // 16 x 128, edges clamped
    conv3x3_mma_kernel<<<grid, NTHREADS, smem>>>(x, w, out);
}